// round 1
// baseline (speedup 1.0000x reference)
#include <cuda_runtime.h>
#include <cstdint>

// Problem constants (fixed by the reference)
static constexpr int B  = 2048;   // batch
static constexpr int U  = 256;    // units
static constexpr int P  = 256;    // features
static constexpr int G  = 64;     // groups
static constexpr int UT = 16;     // unit tile per CTA

#define SOFTPLUS_C 0.5413248546129181f

// Scratch (allocation-free rule: __device__ globals)
__device__ float g_sp_w[(size_t)G * U * P];   // softplus(C + w_sigma), 16.7 MB
__device__ int   g_items[B];                  // batch indices sorted by group
__device__ int   g_start[G + 1];              // group offsets into g_items

__device__ __forceinline__ float softplus_f(float v) {
    // numerically stable: max(v,0) + log1p(exp(-|v|))  (matches jax.nn.softplus in f32)
    return fmaxf(v, 0.0f) + log1pf(expf(-fabsf(v)));
}

// ---------------------------------------------------------------------------
// Kernel 1: precompute softplus(C + w_sigma) once per (g,u,p)
// ---------------------------------------------------------------------------
__global__ void sp_precompute_kernel(const float* __restrict__ w_sigma) {
    size_t i4 = (size_t)blockIdx.x * blockDim.x + threadIdx.x;
    const size_t n4 = (size_t)G * U * P / 4;
    if (i4 >= n4) return;
    float4 v = reinterpret_cast<const float4*>(w_sigma)[i4];
    float4 r;
    r.x = softplus_f(SOFTPLUS_C + v.x);
    r.y = softplus_f(SOFTPLUS_C + v.y);
    r.z = softplus_f(SOFTPLUS_C + v.z);
    r.w = softplus_f(SOFTPLUS_C + v.w);
    reinterpret_cast<float4*>(g_sp_w)[i4] = r;
}

// ---------------------------------------------------------------------------
// Kernel 2: counting-sort batches by group (single block)
// ---------------------------------------------------------------------------
__global__ void bin_kernel(const int* __restrict__ gid) {
    __shared__ int cnt[G];
    __shared__ int off[G];
    int tid = threadIdx.x;
    if (tid < G) cnt[tid] = 0;
    __syncthreads();
    for (int b = tid; b < B; b += blockDim.x)
        atomicAdd(&cnt[gid[b]], 1);
    __syncthreads();
    if (tid == 0) {
        int s = 0;
        for (int g = 0; g < G; g++) {
            g_start[g] = s;
            off[g] = s;
            s += cnt[g];
        }
        g_start[G] = s;
    }
    __syncthreads();
    for (int b = tid; b < B; b += blockDim.x) {
        int g = gid[b];
        int pos = atomicAdd(&off[g], 1);
        g_items[pos] = b;   // order within group is nondeterministic but outputs
                            // are per-batch independent -> results deterministic
    }
}

// ---------------------------------------------------------------------------
// Kernel 3: main streaming kernel.
// grid = (U/UT, G). CTA (ux, g) owns units [ux*UT, ux*UT+UT) of group g.
// Keeps w_mu / sp_w tile in SMEM (reused across ~32 batches of the group),
// streams eps_w once with coalesced float4 loads. Warp-per-unit dot + shfl.
// ---------------------------------------------------------------------------
__global__ __launch_bounds__(256) void multilevel_dense_kernel(
    const float* __restrict__ x,
    const float* __restrict__ w_mu,
    const float* __restrict__ b_mu,
    const float* __restrict__ b_sigma,
    const float* __restrict__ eps_w,
    const float* __restrict__ eps_b,
    float* __restrict__ out)
{
    __shared__ float s_wmu[UT * P];
    __shared__ float s_sp [UT * P];
    __shared__ float s_x  [P];

    const int g   = blockIdx.y;
    const int u0  = blockIdx.x * UT;
    const int tid = threadIdx.x;
    const int warp = tid >> 5;
    const int lane = tid & 31;

    // Load the (group, unit-tile) weight slabs into SMEM (float4, coalesced)
    {
        const float4* wm4 = reinterpret_cast<const float4*>(w_mu  + ((size_t)g * U + u0) * P);
        const float4* sp4 = reinterpret_cast<const float4*>(g_sp_w + ((size_t)g * U + u0) * P);
        float4* swm = reinterpret_cast<float4*>(s_wmu);
        float4* ssp = reinterpret_cast<float4*>(s_sp);
        #pragma unroll
        for (int i = tid; i < UT * P / 4; i += 256) {
            swm[i] = wm4[i];
            ssp[i] = sp4[i];
        }
    }

    // Per-unit bias constants (2 units per warp), computed by all lanes (cheap)
    float bmu_c[2], spb_c[2];
    #pragma unroll
    for (int t = 0; t < 2; t++) {
        int u = u0 + warp * 2 + t;
        bmu_c[t] = b_mu[g * U + u];
        spb_c[t] = softplus_f(SOFTPLUS_C + b_sigma[g * U + u]);
    }

    const int start = g_start[g];
    const int end   = g_start[g + 1];

    for (int idx = start; idx < end; ++idx) {
        const int b = g_items[idx];
        __syncthreads();                       // protect s_x from prev iter (and slab load on iter 0)
        s_x[tid] = x[(size_t)b * P + tid];
        __syncthreads();

        const float4* sx4 = reinterpret_cast<const float4*>(s_x);

        #pragma unroll
        for (int t = 0; t < 2; t++) {
            const int lu = warp * 2 + t;
            const int u  = u0 + lu;
            const float4* e4  = reinterpret_cast<const float4*>(eps_w + ((size_t)b * U + u) * P);
            const float4* wm4 = reinterpret_cast<const float4*>(s_wmu + lu * P);
            const float4* sp4 = reinterpret_cast<const float4*>(s_sp  + lu * P);

            float acc = 0.0f;
            #pragma unroll
            for (int j = 0; j < 2; j++) {
                const int q = j * 32 + lane;   // float4 index within the 256-wide row
                float4 ev = e4[q];
                float4 wv = wm4[q];
                float4 sv = sp4[q];
                float4 xv = sx4[q];
                acc = fmaf(fmaf(sv.x, ev.x, wv.x), xv.x, acc);
                acc = fmaf(fmaf(sv.y, ev.y, wv.y), xv.y, acc);
                acc = fmaf(fmaf(sv.z, ev.z, wv.z), xv.z, acc);
                acc = fmaf(fmaf(sv.w, ev.w, wv.w), xv.w, acc);
            }
            #pragma unroll
            for (int o = 16; o; o >>= 1)
                acc += __shfl_down_sync(0xffffffffu, acc, o);
            if (lane == 0) {
                float bias = bmu_c[t] + spb_c[t] * eps_b[(size_t)b * U + u];
                out[(size_t)b * U + u] = acc + bias;
            }
        }
    }
}

// ---------------------------------------------------------------------------
// Launch
// Input order (metadata): x, gid, w_mu, w_sigma, b_mu, b_sigma, eps_w, eps_b
// ---------------------------------------------------------------------------
extern "C" void kernel_launch(void* const* d_in, const int* in_sizes, int n_in,
                              void* d_out, int out_size) {
    const float* x       = (const float*)d_in[0];
    const int*   gid     = (const int*)  d_in[1];
    const float* w_mu    = (const float*)d_in[2];
    const float* w_sigma = (const float*)d_in[3];
    const float* b_mu    = (const float*)d_in[4];
    const float* b_sigma = (const float*)d_in[5];
    const float* eps_w   = (const float*)d_in[6];
    const float* eps_b   = (const float*)d_in[7];
    float* out = (float*)d_out;

    // 1) softplus(C + w_sigma) -> g_sp_w
    {
        const size_t n4 = (size_t)G * U * P / 4;   // 1,048,576 float4s
        int threads = 256;
        int blocks = (int)((n4 + threads - 1) / threads);
        sp_precompute_kernel<<<blocks, threads>>>(w_sigma);
    }
    // 2) bin batches by group
    bin_kernel<<<1, 256>>>(gid);
    // 3) main kernel
    {
        dim3 grid(U / UT, G);   // (16, 64) = 1024 CTAs
        multilevel_dense_kernel<<<grid, 256>>>(x, w_mu, b_mu, b_sigma,
                                               eps_w, eps_b, out);
    }
}